// round 7
// baseline (speedup 1.0000x reference)
#include <cuda_runtime.h>
#include <stdint.h>

#define D 768
#define H 64
#define E 7
#define BMAX 32768

// ---------------- device scratch ----------------
__device__ int d_offsets[E + 1];
__device__ int d_perm[BMAX];
__device__ float d_w1c[E * D * H];   // tf32-rounded W1
__device__ float d_w2c[E * H * D];   // tf32-rounded W2

// ---------------- helpers ----------------
__device__ __forceinline__ uint32_t smem_u32(const void* p) {
    uint32_t a;
    asm("{ .reg .u64 t; cvta.to.shared.u64 t, %1; cvt.u32.u64 %0, t; }" : "=r"(a) : "l"(p));
    return a;
}
__device__ __forceinline__ float f2tf(float f) {
    uint32_t u;
    asm("cvt.rna.tf32.f32 %0, %1;" : "=r"(u) : "f"(f));
    return __uint_as_float(u);
}
__device__ __forceinline__ uint32_t f2tfu(float f) {
    uint32_t u;
    asm("cvt.rna.tf32.f32 %0, %1;" : "=r"(u) : "f"(f));
    return u;
}
__device__ __forceinline__ void cpa16(uint32_t dst, const void* src) {
    asm volatile("cp.async.cg.shared.global [%0], [%1], 16;" :: "r"(dst), "l"(src));
}
#define CP_COMMIT() asm volatile("cp.async.commit_group;" ::: "memory")
#define CP_WAIT1()  asm volatile("cp.async.wait_group 1;" ::: "memory")
#define CP_WAIT0()  asm volatile("cp.async.wait_group 0;" ::: "memory")

__device__ __forceinline__ void mma_tf32(float* c, const uint32_t* a, uint32_t b0, uint32_t b1) {
    asm volatile(
        "mma.sync.aligned.m16n8k8.row.col.f32.tf32.tf32.f32 "
        "{%0,%1,%2,%3}, {%4,%5,%6,%7}, {%8,%9}, {%0,%1,%2,%3};\n"
        : "+f"(c[0]), "+f"(c[1]), "+f"(c[2]), "+f"(c[3])
        : "r"(a[0]), "r"(a[1]), "r"(a[2]), "r"(a[3]), "r"(b0), "r"(b1));
}

// ---------------- fused scaffold: probe + stable counting sort (1 CTA) ----------------
__global__ void __launch_bounds__(1024) k_prep(const void* __restrict__ ids, int B) {
    __shared__ int cnt[E * 1024];
    __shared__ int tot[E];
    __shared__ int off[E];
    __shared__ int s_bad;
    const int t = threadIdx.x;
    if (t == 0) s_bad = 0;
    __syncthreads();
    {   // dtype probe: int64 ids all in [0,E); int32 viewed as int64 won't be
        const long long* p = (const long long*)ids;
        int n = min(B / 2, 1024);
        if (t < n) { long long v = p[t]; if (v < 0 || v >= E) s_bad = 1; }
    }
    __syncthreads();
    const int is64 = !s_bad;
    const int nPer = (B + 1023) >> 10;
    const int base = t * nPer;
    unsigned long long c64 = 0;  // 7 packed 8-bit counters
#pragma unroll 4
    for (int j = 0; j < nPer; j++) {
        int i = base + j;
        if (i < B) {
            int e = is64 ? (int)((const long long*)ids)[i] : ((const int*)ids)[i];
            c64 += 1ull << (e * 8);
        }
    }
#pragma unroll
    for (int e = 0; e < E; e++) cnt[e * 1024 + t] = (int)((c64 >> (e * 8)) & 255);
    __syncthreads();
    // per-expert exclusive scan over 1024 thread-counts (warp e handles expert e)
    const int wid = t >> 5, lane = t & 31;
    if (wid < E) {
        int* ce = cnt + wid * 1024;
        const int i0 = lane * 32;
        int s = 0;
        for (int j = 0; j < 32; j++) s += ce[i0 + j];
        int pre = s;
#pragma unroll
        for (int dd = 1; dd < 32; dd <<= 1) {
            int v = __shfl_up_sync(0xffffffffu, pre, dd);
            if (lane >= dd) pre += v;
        }
        if (lane == 31) tot[wid] = pre;
        int run = pre - s;
        for (int j = 0; j < 32; j++) { int v = ce[i0 + j]; ce[i0 + j] = run; run += v; }
    }
    __syncthreads();
    if (t == 0) {
        int a = 0;
        for (int e = 0; e < E; e++) { off[e] = a; d_offsets[e] = a; a += tot[e]; }
        d_offsets[E] = a;
    }
    __syncthreads();
    unsigned long long r64 = 0;
    for (int j = 0; j < nPer; j++) {
        int i = base + j;
        if (i < B) {
            int e = is64 ? (int)((const long long*)ids)[i] : ((const int*)ids)[i];
            int pos = off[e] + cnt[e * 1024 + t] + (int)((r64 >> (e * 8)) & 255);
            d_perm[pos] = i;
            r64 += 1ull << (e * 8);
        }
    }
}

// ---------------- one-time tf32 rounding of weights ----------------
__global__ void k_wcvt(const float* __restrict__ W1, const float* __restrict__ W2) {
    const int n = E * D * H;
    for (int i = blockIdx.x * blockDim.x + threadIdx.x; i < n; i += gridDim.x * blockDim.x) {
        d_w1c[i] = f2tf(W1[i]);
        d_w2c[i] = f2tf(W2[i]);
    }
}

// ---------------- smem layout (float offsets) ----------------
#define XS_LD 36
#define W_LD 72
#define HS_LD 68
#define OFF_HS 0                 // 64*68 = 4352
#define OFF_U  4352              // union: 9216 floats
#define OFF_B1 13568             // 64
#define OFF_B2 13632             // 768
#define OFF_RI 14400             // 64 ints
#define SMEM_FLOATS 14464
#define SMEM_BYTES (SMEM_FLOATS * 4)   // 57856

// ---------------- main kernel: M=64, cp.async double-buffered ----------------
__global__ void __launch_bounds__(128)
k_main(const float* __restrict__ x, const float* __restrict__ b1,
       const float* __restrict__ b2, float* __restrict__ out)
{
    const int e = blockIdx.y;
    const int seg0 = d_offsets[e], seg1 = d_offsets[e + 1];
    const int row0 = seg0 + blockIdx.x * 64;
    if (row0 >= seg1) return;
    const int nrows = min(64, seg1 - row0);

    extern __shared__ float sm[];
    float* Hs  = sm + OFF_HS;
    float* b1s = sm + OFF_B1;
    float* b2s = sm + OFF_B2;
    int*   rowI = (int*)(sm + OFF_RI);
    const uint32_t sb = smem_u32(sm);
    const uint32_t uXs[2] = { sb + OFF_U * 4u, sb + (OFF_U + 2304) * 4u };
    const uint32_t uW1[2] = { sb + (OFF_U + 4608) * 4u, sb + (OFF_U + 6912) * 4u };
    const uint32_t uW2[2] = { sb + OFF_U * 4u, sb + (OFF_U + 4608) * 4u };
    float* const fXs[2] = { sm + OFF_U, sm + OFF_U + 2304 };
    float* const fW1[2] = { sm + OFF_U + 4608, sm + OFF_U + 6912 };
    float* const fW2[2] = { sm + OFF_U, sm + OFF_U + 4608 };

    const int tid = threadIdx.x;
    const int w = tid >> 5, lane = tid & 31;
    const int g = lane >> 2, tig = lane & 3;

    if (tid < 64) {
        rowI[tid] = d_perm[row0 + min(tid, nrows - 1)];
        b1s[tid] = b1[e * H + tid];
    }
    for (int i = tid; i < D; i += 128) b2s[i] = b2[e * D + i];
    __syncthreads();

    const float* W1e = d_w1c + (size_t)e * D * H;
    const float* W2e = d_w2c + (size_t)e * H * D;

    // gather source (row tid>>1, half tid&1 => 16 floats = 4x16B per thread per chunk)
    const float* xg = x + (size_t)rowI[tid >> 1] * D + (tid & 1) * 16;
    const uint32_t xdst = ((tid >> 1) * XS_LD + (tid & 1) * 16) * 4u;
    const int kW1 = tid >> 2, cq1 = (tid & 3) * 16;
    const uint32_t w1dst = (kW1 * W_LD + cq1) * 4u;

    // prefetch GEMM1 chunk 0
    {
        const float* ws = W1e + kW1 * H + cq1;
#pragma unroll
        for (int q = 0; q < 4; q++) cpa16(uXs[0] + xdst + q * 16, xg + q * 4);
#pragma unroll
        for (int q = 0; q < 4; q++) cpa16(uW1[0] + w1dst + q * 16, ws + q * 4);
    }
    CP_COMMIT();

    // ============ GEMM1: h = relu(X @ W1 + b1), 24 K-chunks of 32 ============
    float acc[8][4];
#pragma unroll
    for (int nt = 0; nt < 8; nt++)
#pragma unroll
        for (int q = 0; q < 4; q++) acc[nt][q] = 0.f;

#pragma unroll 2
    for (int i = 0; i < 24; i++) {
        const int b = i & 1;
        if (i < 23) {
            const int nb = (i + 1) & 1, kc = (i + 1) * 32;
            const float* ws = W1e + (kc + kW1) * H + cq1;
#pragma unroll
            for (int q = 0; q < 4; q++) cpa16(uXs[nb] + xdst + q * 16, xg + kc + q * 4);
#pragma unroll
            for (int q = 0; q < 4; q++) cpa16(uW1[nb] + w1dst + q * 16, ws + q * 4);
            CP_COMMIT();
            CP_WAIT1();
        } else {
            CP_WAIT0();
        }
        __syncthreads();
        const float* Xb = fXs[b];
        const float* Wb = fW1[b];
#pragma unroll
        for (int ks = 0; ks < 4; ks++) {
            const int kb = ks * 8;
            uint32_t af[4];
            af[0] = f2tfu(Xb[(w * 16 + g) * XS_LD + kb + tig]);
            af[1] = f2tfu(Xb[(w * 16 + g + 8) * XS_LD + kb + tig]);
            af[2] = f2tfu(Xb[(w * 16 + g) * XS_LD + kb + tig + 4]);
            af[3] = f2tfu(Xb[(w * 16 + g + 8) * XS_LD + kb + tig + 4]);
#pragma unroll
            for (int nt = 0; nt < 8; nt++) {
                uint32_t b0 = __float_as_uint(Wb[(kb + tig) * W_LD + nt * 8 + g]);
                uint32_t bb = __float_as_uint(Wb[(kb + tig + 4) * W_LD + nt * 8 + g]);
                mma_tf32(acc[nt], af, b0, bb);
            }
        }
        __syncthreads();
    }

    // epilogue1: Hs = tf32(relu(acc + b1)) (float2 stores)
#pragma unroll
    for (int nt = 0; nt < 8; nt++) {
        const int c = nt * 8 + tig * 2;
        float v0 = acc[nt][0] + b1s[c];
        float v1 = acc[nt][1] + b1s[c + 1];
        float v2 = acc[nt][2] + b1s[c];
        float v3 = acc[nt][3] + b1s[c + 1];
        float2 lo = make_float2(f2tf(v0 > 0.f ? v0 : 0.f), f2tf(v1 > 0.f ? v1 : 0.f));
        float2 hi = make_float2(f2tf(v2 > 0.f ? v2 : 0.f), f2tf(v3 > 0.f ? v3 : 0.f));
        *(float2*)(Hs + (w * 16 + g) * HS_LD + c)     = lo;
        *(float2*)(Hs + (w * 16 + g + 8) * HS_LD + c) = hi;
    }

    // prefetch GEMM2 chunk 0 (union free after GEMM1's final sync)
    const int kW2 = tid >> 1, hf2 = (tid & 1) * 32;
    const uint32_t w2dst = (kW2 * W_LD + hf2) * 4u;
    {
        const float* ws = W2e + kW2 * D + hf2;
#pragma unroll
        for (int q = 0; q < 8; q++) cpa16(uW2[0] + w2dst + q * 16, ws + q * 4);
    }
    CP_COMMIT();

    // per-thread row contexts for epilogue2
    const int rlo = w * 16 + g, rhi = rlo + 8;
    const bool vlo = rlo < nrows, vhi = rhi < nrows;
    const float* xlo = x + (size_t)rowI[rlo] * D;
    const float* xhi = x + (size_t)rowI[rhi] * D;
    float* olo = out + (size_t)rowI[rlo] * D;
    float* ohi = out + (size_t)rowI[rhi] * D;

    // ============ GEMM2: out = x + h @ W2 + b2, 12 N-chunks of 64 ============
#pragma unroll 2
    for (int j = 0; j < 12; j++) {
        const int b = j & 1;
        if (j < 11) {
            const int nb = (j + 1) & 1;
            const float* ws = W2e + kW2 * D + (j + 1) * 64 + hf2;
#pragma unroll
            for (int q = 0; q < 8; q++) cpa16(uW2[nb] + w2dst + q * 16, ws + q * 4);
            CP_COMMIT();
            CP_WAIT1();
        } else {
            CP_WAIT0();
        }
        __syncthreads();

        float acc2[8][4];
#pragma unroll
        for (int nt = 0; nt < 8; nt++)
#pragma unroll
            for (int q = 0; q < 4; q++) acc2[nt][q] = 0.f;

        const float* Wb = fW2[b];
#pragma unroll
        for (int ks = 0; ks < 8; ks++) {
            const int kb = ks * 8;
            uint32_t af[4];
            af[0] = __float_as_uint(Hs[rlo * HS_LD + kb + tig]);
            af[1] = __float_as_uint(Hs[rhi * HS_LD + kb + tig]);
            af[2] = __float_as_uint(Hs[rlo * HS_LD + kb + tig + 4]);
            af[3] = __float_as_uint(Hs[rhi * HS_LD + kb + tig + 4]);
#pragma unroll
            for (int nt = 0; nt < 8; nt++) {
                uint32_t b0 = __float_as_uint(Wb[(kb + tig) * W_LD + nt * 8 + g]);
                uint32_t bb = __float_as_uint(Wb[(kb + tig + 4) * W_LD + nt * 8 + g]);
                mma_tf32(acc2[nt], af, b0, bb);
            }
        }
        __syncthreads();   // release buffer b before next prefetch overwrites it

        // fused epilogue: out = x + y + b2 (overlaps next chunk's cp.async)
#pragma unroll
        for (int nt = 0; nt < 8; nt++) {
            const int col = j * 64 + nt * 8 + tig * 2;
            float2 bv = *(const float2*)(b2s + col);
            if (vlo) {
                float2 xv = *(const float2*)(xlo + col);
                float2 o = make_float2(xv.x + acc2[nt][0] + bv.x,
                                       xv.y + acc2[nt][1] + bv.y);
                *(float2*)(olo + col) = o;
            }
            if (vhi) {
                float2 xv = *(const float2*)(xhi + col);
                float2 o = make_float2(xv.x + acc2[nt][2] + bv.x,
                                       xv.y + acc2[nt][3] + bv.y);
                *(float2*)(ohi + col) = o;
            }
        }
    }
}

extern "C" void kernel_launch(void* const* d_in, const int* in_sizes, int n_in,
                              void* d_out, int out_size)
{
    const float* x   = (const float*)d_in[0];
    const void*  ids = d_in[1];
    const float* W1  = (const float*)d_in[2];
    const float* b1  = (const float*)d_in[3];
    const float* W2  = (const float*)d_in[4];
    const float* b2  = (const float*)d_in[5];
    float*       out = (float*)d_out;

    const int B = in_sizes[1];

    k_prep<<<1, 1024>>>(ids, B);
    k_wcvt<<<688, 512>>>(W1, W2);

    cudaFuncSetAttribute(k_main, cudaFuncAttributeMaxDynamicSharedMemorySize, SMEM_BYTES);
    dim3 grid((B + 63) / 64, E);
    k_main<<<grid, 128, SMEM_BYTES>>>(x, b1, b2, out);
}

// round 8
// speedup vs baseline: 1.6251x; 1.6251x over previous
#include <cuda_runtime.h>
#include <cuda_fp16.h>
#include <stdint.h>

#define D 768
#define H 64
#define E 7
#define BMAX 32768
#define NHB 64            // histogram blocks

// ---------------- device scratch ----------------
__device__ int d_offsets[E + 1];
__device__ int d_cursor[E];
__device__ int d_blk[NHB * E];
__device__ int d_perm[BMAX];
__device__ int d_is64;
__device__ __align__(16) __half d_w1t[E * H * D];   // [e][n(H)][k(D)] fp16
__device__ __align__(16) __half d_w2t[E * D * H];   // [e][n(D)][k(H)] fp16

// ---------------- helpers ----------------
__device__ __forceinline__ uint32_t smem_u32(const void* p) {
    uint32_t a;
    asm("{ .reg .u64 t; cvta.to.shared.u64 t, %1; cvt.u32.u64 %0, t; }" : "=r"(a) : "l"(p));
    return a;
}
__device__ __forceinline__ uint32_t pack2(float a, float b) {
    __half2 h = __floats2half2_rn(a, b);
    return *(uint32_t*)&h;
}
__device__ __forceinline__ void cpa16(uint32_t dst, const void* src) {
    asm volatile("cp.async.cg.shared.global [%0], [%1], 16;" :: "r"(dst), "l"(src));
}
#define CP_COMMIT() asm volatile("cp.async.commit_group;" ::: "memory")
#define CP_WAIT0()  asm volatile("cp.async.wait_group 0;" ::: "memory")
#define LDM4(r0, r1, r2, r3, addr) \
    asm volatile("ldmatrix.sync.aligned.m8n8.x4.shared.b16 {%0,%1,%2,%3}, [%4];" \
        : "=r"(r0), "=r"(r1), "=r"(r2), "=r"(r3) : "r"(addr))

__device__ __forceinline__ void mma_f16(float* c, uint32_t a0, uint32_t a1, uint32_t a2,
                                        uint32_t a3, uint32_t b0, uint32_t b1) {
    asm volatile(
        "mma.sync.aligned.m16n8k16.row.col.f32.f16.f16.f32 "
        "{%0,%1,%2,%3}, {%4,%5,%6,%7}, {%8,%9}, {%0,%1,%2,%3};\n"
        : "+f"(c[0]), "+f"(c[1]), "+f"(c[2]), "+f"(c[3])
        : "r"(a0), "r"(a1), "r"(a2), "r"(a3), "r"(b0), "r"(b1));
}

__device__ __forceinline__ int load_id(const void* ids, int i, int is64) {
    return is64 ? (int)((const long long*)ids)[i] : ((const int*)ids)[i];
}

// ---------------- launch 1: histogram (+dtype probe) ----------------
__global__ void __launch_bounds__(256) k_hist(const void* __restrict__ ids, int B) {
    __shared__ int sc[E];
    __shared__ int sbad;
    const int t = threadIdx.x;
    if (t < E) sc[t] = 0;
    if (t == 0) sbad = 0;
    __syncthreads();
    {   // probe: int64 ids all in [0,E); int32 viewed as int64 fails w.p. ~1
        const long long* p = (const long long*)ids;
        int n = min(B / 2, 256);
        if (t < n) { long long v = p[t]; if (v < 0 || v >= E) sbad = 1; }
    }
    __syncthreads();
    const int is64 = !sbad;
    if (t == 0 && blockIdx.x == 0) d_is64 = is64;
    for (int i = blockIdx.x * 256 + t; i < B; i += NHB * 256) {
        int e = load_id(ids, i, is64);
        if ((unsigned)e < E) atomicAdd(&sc[e], 1);
    }
    __syncthreads();
    if (t < E) d_blk[blockIdx.x * E + t] = sc[t];
}

// ---------------- launch 2: tiny scan ----------------
__global__ void k_scan() {
    __shared__ int tot[E];
    const int t = threadIdx.x;
    if (t < E) {
        int s = 0;
        for (int b = 0; b < NHB; b++) s += d_blk[b * E + t];
        tot[t] = s;
    }
    __syncthreads();
    if (t == 0) {
        int a = 0;
        for (int e = 0; e < E; e++) { d_offsets[e] = a; d_cursor[e] = a; a += tot[e]; }
        d_offsets[E] = a;
    }
}

// ---------------- launch 3: fused scatter + weight cvt/transpose ----------------
__global__ void __launch_bounds__(256) k_fuse(const void* __restrict__ ids, int B,
                                              const float* __restrict__ W1,
                                              const float* __restrict__ W2) {
    const int blk = blockIdx.x;
    if (blk < NHB) {
        const int is64 = d_is64;
        for (int i = blk * 256 + threadIdx.x; i < B; i += NHB * 256) {
            int e = load_id(ids, i, is64);
            if ((unsigned)e < E) {
                int p = atomicAdd(&d_cursor[e], 1);
                d_perm[p] = i;
            }
        }
    } else {
        const int nb = gridDim.x - NHB;
        const int n1 = E * D * H;
        for (int idx = (blk - NHB) * 256 + threadIdx.x; idx < 2 * n1; idx += nb * 256) {
            if (idx < n1) {   // W1: [e][k(D)][n(H)] -> w1t [e][n][k]
                int e = idx / (D * H);
                int rem = idx - e * D * H;
                int k = rem / H, n = rem - k * H;
                d_w1t[((size_t)e * H + n) * D + k] = __float2half(W1[idx]);
            } else {          // W2: [e][k(H)][n(D)] -> w2t [e][n][k]
                int j = idx - n1;
                int e = j / (H * D);
                int rem = j - e * H * D;
                int k = rem / D, n = rem - k * D;
                d_w2t[((size_t)e * D + n) * H + k] = __float2half(W2[j]);
            }
        }
    }
}

// ---------------- smem layout (bytes) ----------------
// Hs        @ 0      : 64 rows * 144B = 9216
// Xs[2]/W2[2] @ 9216 : 2 * 9216 = 18432  (union)
// W1[2]     @ 27648  : 2 * 9216 = 18432
// b1s f32   @ 46080  : 256
// b2s f32   @ 46336  : 3072
// rowI int  @ 49408  : 256
#define ROWB 144
#define SMEM_BYTES 49664

// ---------------- launch 4: main fp16 mma kernel ----------------
__global__ void __launch_bounds__(128)
k_main(const float* __restrict__ x, const float* __restrict__ b1,
       const float* __restrict__ b2, float* __restrict__ out)
{
    const int e = blockIdx.y;
    const int seg0 = d_offsets[e], seg1 = d_offsets[e + 1];
    const int row0 = seg0 + blockIdx.x * 64;
    if (row0 >= seg1) return;
    const int nrows = min(64, seg1 - row0);

    extern __shared__ char smc[];
    const uint32_t sb = smem_u32(smc);
    float* b1s = (float*)(smc + 46080);
    float* b2s = (float*)(smc + 46336);
    int*   rowI = (int*)(smc + 49408);

    const int tid = threadIdx.x, w = tid >> 5, lane = tid & 31;
    const int g = lane >> 2, tig = lane & 3;

    if (tid < 64) {
        rowI[tid] = d_perm[row0 + min(tid, nrows - 1)];
        b1s[tid] = b1[e * H + tid];
    }
    for (int i = tid; i < D; i += 128) b2s[i] = b2[e * D + i];
    __syncthreads();

    const __half* W1e = d_w1t + (size_t)e * H * D;
    const __half* W2e = d_w2t + (size_t)e * D * H;

    const int r = tid >> 1, s = tid & 1;
    const float* xg = x + (size_t)rowI[r] * D + s * 32;
    const __half* w1_src = W1e + r * D + s * 32;
    const __half* w2_src = W2e + r * H + s * 32;

    const uint32_t xs_dst = sb + 9216 + r * ROWB + s * 64;   // + b*9216
    const uint32_t w1_dst = sb + 27648 + r * ROWB + s * 64;  // + b*9216
    const uint32_t w2_dst = sb + 9216 + r * ROWB + s * 64;   // + b*9216
    const uint32_t a_core = sb + 9216 + (w * 16 + (lane & 15)) * ROWB + ((lane >> 4) & 1) * 16;
    const uint32_t b_core = ((lane & 7) + ((lane >> 4) & 1) * 8) * ROWB + ((lane >> 3) & 1) * 16;

    // ---- prologue: X0 + W1(0) ----
    float4 xr[8];
#pragma unroll
    for (int q = 0; q < 8; q++) xr[q] = __ldg((const float4*)xg + q);
#pragma unroll
    for (int q = 0; q < 4; q++) cpa16(w1_dst + q * 16, w1_src + q * 8);
    CP_COMMIT();
    {
        uint32_t* xd = (uint32_t*)(smc + 9216 + r * ROWB + s * 64);
#pragma unroll
        for (int q = 0; q < 8; q++) {
            xd[2 * q]     = pack2(xr[q].x, xr[q].y);
            xd[2 * q + 1] = pack2(xr[q].z, xr[q].w);
        }
    }
    CP_WAIT0();
    __syncthreads();

    // ============ GEMM1: h = relu(X @ W1^T + b1), 12 K-chunks of 64 ============
    float acc[8][4];
#pragma unroll
    for (int nt = 0; nt < 8; nt++)
#pragma unroll
        for (int q = 0; q < 4; q++) acc[nt][q] = 0.f;

#pragma unroll 1
    for (int i = 0; i < 12; i++) {
        const int b = i & 1;
        if (i < 11) {
            const __half* ws = w1_src + (i + 1) * 64;
            const uint32_t wd = w1_dst + (b ^ 1) * 9216;
#pragma unroll
            for (int q = 0; q < 4; q++) cpa16(wd + q * 16, ws + q * 8);
            CP_COMMIT();
            const float4* xsrc = (const float4*)(xg + (i + 1) * 64);
#pragma unroll
            for (int q = 0; q < 8; q++) xr[q] = __ldg(xsrc + q);
        }
        const uint32_t aB = a_core + b * 9216;
        const uint32_t wB = sb + 27648 + b * 9216 + b_core;
#pragma unroll
        for (int ks = 0; ks < 4; ks++) {
            uint32_t a0, a1, a2, a3;
            LDM4(a0, a1, a2, a3, aB + ks * 32);
#pragma unroll
            for (int j = 0; j < 4; j++) {
                uint32_t r0, r1, r2, r3;
                LDM4(r0, r1, r2, r3, wB + j * 16 * ROWB + ks * 32);
                mma_f16(acc[2 * j],     a0, a1, a2, a3, r0, r1);
                mma_f16(acc[2 * j + 1], a0, a1, a2, a3, r2, r3);
            }
        }
        if (i < 11) {
            uint32_t* xd = (uint32_t*)(smc + 9216 + (b ^ 1) * 9216 + r * ROWB + s * 64);
#pragma unroll
            for (int q = 0; q < 8; q++) {
                xd[2 * q]     = pack2(xr[q].x, xr[q].y);
                xd[2 * q + 1] = pack2(xr[q].z, xr[q].w);
            }
        }
        CP_WAIT0();
        __syncthreads();
    }

    // ---- prefetch W2(0) into union buf0 (Xs released) ----
#pragma unroll
    for (int q = 0; q < 4; q++) cpa16(w2_dst + q * 16, w2_src + q * 8);
    CP_COMMIT();

    // ---- epilogue1: Hs = fp16(relu(acc + b1)) ----
#pragma unroll
    for (int nt = 0; nt < 8; nt++) {
        const int c = nt * 8 + 2 * tig;
        float v0 = acc[nt][0] + b1s[c];
        float v1 = acc[nt][1] + b1s[c + 1];
        float v2 = acc[nt][2] + b1s[c];
        float v3 = acc[nt][3] + b1s[c + 1];
        *(uint32_t*)(smc + (w * 16 + g) * ROWB + c * 2) =
            pack2(v0 > 0.f ? v0 : 0.f, v1 > 0.f ? v1 : 0.f);
        *(uint32_t*)(smc + (w * 16 + g + 8) * ROWB + c * 2) =
            pack2(v2 > 0.f ? v2 : 0.f, v3 > 0.f ? v3 : 0.f);
    }
    __syncthreads();

    // ---- A-fragments of h: loaded ONCE for all 12 N-chunks ----
    uint32_t ha[4][4];
    {
        const uint32_t hA = sb + (w * 16 + (lane & 15)) * ROWB + ((lane >> 4) & 1) * 16;
#pragma unroll
        for (int ks = 0; ks < 4; ks++)
            LDM4(ha[ks][0], ha[ks][1], ha[ks][2], ha[ks][3], hA + ks * 32);
    }
    CP_WAIT0();
    __syncthreads();

    // per-thread row contexts for epilogue2
    const int rlo = w * 16 + g, rhi = rlo + 8;
    const bool vlo = rlo < nrows, vhi = rhi < nrows;
    const float* xlo = x + (size_t)rowI[rlo] * D;
    const float* xhi = x + (size_t)rowI[rhi] * D;
    float* olo = out + (size_t)rowI[rlo] * D;
    float* ohi = out + (size_t)rowI[rhi] * D;

    // ============ GEMM2: out = x + h @ W2^T + b2, 12 N-chunks of 64 ============
#pragma unroll 1
    for (int j = 0; j < 12; j++) {
        const int b = j & 1;
        if (j < 11) {
            const __half* ws = w2_src + (size_t)(j + 1) * 64 * H;
            const uint32_t wd = w2_dst + (b ^ 1) * 9216;
#pragma unroll
            for (int q = 0; q < 4; q++) cpa16(wd + q * 16, ws + q * 8);
            CP_COMMIT();
        }
        float acc2[8][4];
#pragma unroll
        for (int nt = 0; nt < 8; nt++)
#pragma unroll
            for (int q = 0; q < 4; q++) acc2[nt][q] = 0.f;

        const uint32_t wB = sb + 9216 + b * 9216 + b_core;
#pragma unroll
        for (int ks = 0; ks < 4; ks++) {
#pragma unroll
            for (int jt = 0; jt < 4; jt++) {
                uint32_t r0, r1, r2, r3;
                LDM4(r0, r1, r2, r3, wB + jt * 16 * ROWB + ks * 32);
                mma_f16(acc2[2 * jt],     ha[ks][0], ha[ks][1], ha[ks][2], ha[ks][3], r0, r1);
                mma_f16(acc2[2 * jt + 1], ha[ks][0], ha[ks][1], ha[ks][2], ha[ks][3], r2, r3);
            }
        }

        // fused epilogue (overlaps next W2 cp.async)
#pragma unroll
        for (int nt = 0; nt < 8; nt++) {
            const int col = j * 64 + nt * 8 + 2 * tig;
            float2 bv = *(const float2*)(b2s + col);
            if (vlo) {
                float2 xv = *(const float2*)(xlo + col);
                float2 o = make_float2(xv.x + acc2[nt][0] + bv.x,
                                       xv.y + acc2[nt][1] + bv.y);
                *(float2*)(olo + col) = o;
            }
            if (vhi) {
                float2 xv = *(const float2*)(xhi + col);
                float2 o = make_float2(xv.x + acc2[nt][2] + bv.x,
                                       xv.y + acc2[nt][3] + bv.y);
                *(float2*)(ohi + col) = o;
            }
        }
        CP_WAIT0();
        __syncthreads();
    }
}

extern "C" void kernel_launch(void* const* d_in, const int* in_sizes, int n_in,
                              void* d_out, int out_size)
{
    const float* x   = (const float*)d_in[0];
    const void*  ids = d_in[1];
    const float* W1  = (const float*)d_in[2];
    const float* b1  = (const float*)d_in[3];
    const float* W2  = (const float*)d_in[4];
    const float* b2  = (const float*)d_in[5];
    float*       out = (float*)d_out;

    const int B = in_sizes[1];

    k_hist<<<NHB, 256>>>(ids, B);
    k_scan<<<1, 32>>>();
    k_fuse<<<NHB + 84, 256>>>(ids, B, W1, W2);

    cudaFuncSetAttribute(k_main, cudaFuncAttributeMaxDynamicSharedMemorySize, SMEM_BYTES);
    dim3 grid((B + 63) / 64, E);
    k_main<<<grid, 128, SMEM_BYTES>>>(x, b1, b2, out);
}